// round 6
// baseline (speedup 1.0000x reference)
#include <cuda_runtime.h>
#include <math.h>
#include <limits.h>

#define N 8192
#define C 256
#define NCLS 2
#define KNBR 3
#define R2 9.0f
#define DTILE 32

// ---------------- device scratch ----------------
__device__ float g_p[N * C];
__device__ float g_sq[N];
__device__ float g_h[N * C];
__device__ float g_agg[N * C];
__device__ float g_x1s[N * C];
__device__ float g_outs[N * NCLS];
__device__ int   g_idx[N * KNBR];
__device__ float g_W1T[C * C];
__device__ float g_WrelT[C * C];
__device__ float g_WrootT[C * C];

// ---------------- transpose: WT[k][o] = W[o][k] ----------------
__global__ void nv_transpose(const float* __restrict__ W, float* __restrict__ WT) {
    int o = blockIdx.x;
    int k = threadIdx.x;
    WT[k * C + o] = W[o * C + k];
}

// ---------------- softmax + sq norms (serial per row) ----------------
__global__ void nv_softmax(const float* __restrict__ x) {
    int i = blockIdx.x;
    int t = threadIdx.x;
    __shared__ float row[C];
    row[t] = x[i * C + t];
    __syncthreads();
    if (t == 0) {
        float m = row[0];
        for (int k = 1; k < C; ++k) m = fmaxf(m, row[k]);
        float s = 0.f;
        for (int k = 0; k < C; ++k) { row[k] = expf(row[k] - m); s += row[k]; }
        float sq = 0.f;
        for (int k = 0; k < C; ++k) {
            float p = row[k] / s;
            g_p[i * C + k] = p;
            sq += p * p;
        }
        g_sq[i] = sq;
    }
}

// ---------------- h = relu(x @ W1^T + b1), coalesced via W1T ----------------
__global__ void nv_h(const float* __restrict__ x, const float* __restrict__ b1) {
    int i = blockIdx.x, o = threadIdx.x;
    __shared__ float xs[C];
    xs[o] = x[i * C + o];
    __syncthreads();
    float acc = b1[o];
    for (int k = 0; k < C; ++k) acc += xs[k] * g_W1T[k * C + o];
    g_h[i * C + o] = fmaxf(acc, 0.f);
}

// ---------------- full-row distance + top-3 (one pass, no merge) ----------------
// Block handles 8 target rows; 256 threads = (ii = t&7 target, jj = t>>3 source-in-tile).
__global__ void __launch_bounds__(256) nv_dist_top3() {
    __shared__ float pi[8][257];
    __shared__ float tj[DTILE][257];
    __shared__ float cd[8][DTILE * 3];
    __shared__ int   cjx[8][DTILE * 3];

    const int t = threadIdx.x;
    const int ii = t & 7;
    const int jj = t >> 3;
    const int ibase = blockIdx.x * 8;

    for (int e = t; e < 8 * C; e += 256)
        pi[e >> 8][e & 255] = g_p[(size_t)(ibase + (e >> 8)) * C + (e & 255)];
    __syncthreads();

    const float sqi = g_sq[ibase + ii];
    float td[3] = {1e38f, 1e38f, 1e38f};
    int   tjx[3] = {INT_MAX, INT_MAX, INT_MAX};

    for (int j0 = 0; j0 < N; j0 += DTILE) {
        for (int e = t; e < DTILE * C; e += 256)
            tj[e >> 8][e & 255] = g_p[(size_t)(j0 + (e >> 8)) * C + (e & 255)];
        __syncthreads();

        float acc = 0.f;
        for (int k = 0; k < C; ++k) acc += pi[ii][k] * tj[jj][k];

        const int j = j0 + jj;
        const float d = sqi + g_sq[j] - 2.f * acc;

        // bubble-insert into sorted top-3 (lexicographic (d, j))
        if (d < td[2] || (d == td[2] && j < tjx[2])) {
            td[2] = d; tjx[2] = j;
            if (td[2] < td[1] || (td[2] == td[1] && tjx[2] < tjx[1])) {
                float tp = td[1]; td[1] = td[2]; td[2] = tp;
                int ti = tjx[1]; tjx[1] = tjx[2]; tjx[2] = ti;
            }
            if (td[1] < td[0] || (td[1] == td[0] && tjx[1] < tjx[0])) {
                float tp = td[0]; td[0] = td[1]; td[1] = tp;
                int ti = tjx[0]; tjx[0] = tjx[1]; tjx[1] = ti;
            }
        }
        __syncthreads();
    }

    for (int s = 0; s < 3; ++s) {
        cd[ii][jj * 3 + s] = td[s];
        cjx[ii][jj * 3 + s] = tjx[s];
    }
    __syncthreads();

    if (t < 8) {
        float fd[3] = {1e38f, 1e38f, 1e38f};
        int   fj[3] = {INT_MAX, INT_MAX, INT_MAX};
        for (int c2 = 0; c2 < DTILE * 3; ++c2) {
            float d = cd[t][c2]; int j = cjx[t][c2];
            if (d < fd[2] || (d == fd[2] && j < fj[2])) {
                fd[2] = d; fj[2] = j;
                if (fd[2] < fd[1] || (fd[2] == fd[1] && fj[2] < fj[1])) {
                    float tp = fd[1]; fd[1] = fd[2]; fd[2] = tp;
                    int ti = fj[1]; fj[1] = fj[2]; fj[2] = ti;
                }
                if (fd[1] < fd[0] || (fd[1] == fd[0] && fj[1] < fj[0])) {
                    float tp = fd[0]; fd[0] = fd[1]; fd[1] = tp;
                    int ti = fj[0]; fj[0] = fj[1]; fj[1] = ti;
                }
            }
        }
        const int gi = ibase + t;
        for (int s = 0; s < 3; ++s)
            g_idx[gi * KNBR + s] = (fd[s] <= R2) ? fj[s] : -1;
    }
}

// ---------------- neighbor aggregation ----------------
__global__ void nv_agg() {
    int i = blockIdx.x, c2 = threadIdx.x;
    float a = 0.f;
    for (int k = 0; k < KNBR; ++k) {
        int j = g_idx[i * KNBR + k];
        if (j >= 0) a += g_h[(size_t)j * C + c2];
    }
    g_agg[(size_t)i * C + c2] = a;
}

// ---------------- x1 = relu(agg @ Wrel^T + brel + h @ Wroot^T) ----------------
__global__ void nv_x1(const float* __restrict__ brel, float* __restrict__ x1) {
    int i = blockIdx.x, o = threadIdx.x;
    __shared__ float as_[C], hs[C];
    as_[o] = g_agg[(size_t)i * C + o];
    hs[o]  = g_h[(size_t)i * C + o];
    __syncthreads();
    float acc = brel[o];
    for (int k = 0; k < C; ++k)
        acc += as_[k] * g_WrelT[k * C + o] + hs[k] * g_WrootT[k * C + o];
    x1[(size_t)i * C + o] = fmaxf(acc, 0.f);
}

// ---------------- out = x1 @ W2^T + b2 (serial per row) ----------------
__global__ void nv_head(const float* __restrict__ x1, const float* __restrict__ W2,
                        const float* __restrict__ b2, float* __restrict__ out) {
    int i = blockIdx.x, t = threadIdx.x;
    __shared__ float xs[C];
    xs[t] = x1[(size_t)i * C + t];
    __syncthreads();
    if (t == 0) {
        for (int cls = 0; cls < NCLS; ++cls) {
            float a = b2[cls];
            for (int k = 0; k < C; ++k) a += xs[k] * W2[cls * C + k];
            out[i * NCLS + cls] = a;
        }
    }
}

// ---------------- launch ----------------
extern "C" void kernel_launch(void* const* d_in, const int* in_sizes, int n_in,
                              void* d_out, int out_size) {
    const float *x = 0, *W1 = 0, *b1 = 0, *Wrel = 0, *brel = 0, *Wroot = 0, *W2 = 0, *b2 = 0;
    int nw = 0, nb = 0;
    for (int i = 0; i < n_in; ++i) {
        const float* p = (const float*)d_in[i];
        const int s = in_sizes[i];
        if (s == N * C) x = p;
        else if (s == C * C) { if (nw == 0) W1 = p; else if (nw == 1) Wrel = p; else Wroot = p; ++nw; }
        else if (s == C) { if (nb == 0) b1 = p; else brel = p; ++nb; }
        else if (s == NCLS * C) W2 = p;
        else if (s == NCLS) b2 = p;
    }

    // Tuple layout (out, x1) when the buffer holds both; never write past out_size.
    float *x1dst, *outdst;
    float *x1_scr, *out_scr;
    cudaGetSymbolAddress((void**)&x1_scr, g_x1s);
    cudaGetSymbolAddress((void**)&out_scr, g_outs);
    if (out_size >= N * NCLS + N * C) {
        outdst = (float*)d_out;
        x1dst  = outdst + (size_t)N * NCLS;
    } else if (out_size == N * C) {
        x1dst  = (float*)d_out;
        outdst = out_scr;
    } else {
        outdst = (float*)d_out;
        x1dst  = x1_scr;
    }

    float *w1t, *wrelt, *wroott;
    cudaGetSymbolAddress((void**)&w1t, g_W1T);
    cudaGetSymbolAddress((void**)&wrelt, g_WrelT);
    cudaGetSymbolAddress((void**)&wroott, g_WrootT);

    nv_transpose<<<C, C>>>(W1, w1t);
    nv_transpose<<<C, C>>>(Wrel, wrelt);
    nv_transpose<<<C, C>>>(Wroot, wroott);
    nv_softmax<<<N, C>>>(x);
    nv_h<<<N, C>>>(x, b1);
    nv_dist_top3<<<N / 8, 256>>>();
    nv_agg<<<N, C>>>();
    nv_x1<<<N, C>>>(brel, x1dst);
    nv_head<<<N, C>>>(x1dst, W2, b2, outdst);
}

// round 7
// speedup vs baseline: 3.1076x; 3.1076x over previous
#include <cuda_runtime.h>
#include <math.h>
#include <limits.h>

#define N 8192
#define C 256
#define NCLS 2
#define KNBR 3
#define R2 9.0f

// ---------------- device scratch ----------------
__device__ float g_p[N * C];
__device__ float g_sq[N];
__device__ float g_h[N * C];
__device__ float g_agg[N * C];
__device__ float g_x1s[N * C];
__device__ float g_outs[N * NCLS];
__device__ int   g_idx[N * KNBR];
__device__ float g_W1T[C * C];
__device__ float g_WrelT[C * C];
__device__ float g_WrootT[C * C];
__device__ float g_part_d[2 * N * KNBR];
__device__ int   g_part_j[2 * N * KNBR];

// ---------------- helpers ----------------
__device__ __forceinline__ void insert3(float d, int j, float bd[3], int bj[3]) {
    bool l2 = (d < bd[2]) || (d == bd[2] && j < bj[2]);
    if (!l2) return;
    bool l1 = (d < bd[1]) || (d == bd[1] && j < bj[1]);
    bool l0 = (d < bd[0]) || (d == bd[0] && j < bj[0]);
    if (l0) {
        bd[2] = bd[1]; bj[2] = bj[1];
        bd[1] = bd[0]; bj[1] = bj[0];
        bd[0] = d;     bj[0] = j;
    } else if (l1) {
        bd[2] = bd[1]; bj[2] = bj[1];
        bd[1] = d;     bj[1] = j;
    } else {
        bd[2] = d;     bj[2] = j;
    }
}

// ---------------- transpose: WT[k][o] = W[o][k] (unchanged from R6) ----------------
__global__ void nv_transpose(const float* __restrict__ W, float* __restrict__ WT) {
    int o = blockIdx.x;
    int k = threadIdx.x;
    WT[k * C + o] = W[o * C + k];
}

// ---------------- softmax + sq norms (unchanged from R6 — known good) ----------------
__global__ void nv_softmax(const float* __restrict__ x) {
    int i = blockIdx.x;
    int t = threadIdx.x;
    __shared__ float row[C];
    row[t] = x[i * C + t];
    __syncthreads();
    if (t == 0) {
        float m = row[0];
        for (int k = 1; k < C; ++k) m = fmaxf(m, row[k]);
        float s = 0.f;
        for (int k = 0; k < C; ++k) { row[k] = expf(row[k] - m); s += row[k]; }
        float sq = 0.f;
        for (int k = 0; k < C; ++k) {
            float p = row[k] / s;
            g_p[i * C + k] = p;
            sq += p * p;
        }
        g_sq[i] = sq;
    }
}

// ---------------- h = relu(x @ W1^T + b1) (unchanged from R6) ----------------
__global__ void nv_h(const float* __restrict__ x, const float* __restrict__ b1) {
    int i = blockIdx.x, o = threadIdx.x;
    __shared__ float xs[C];
    xs[o] = x[i * C + o];
    __syncthreads();
    float acc = b1[o];
    for (int k = 0; k < C; ++k) acc += xs[k] * g_W1T[k * C + o];
    g_h[i * C + o] = fmaxf(acc, 0.f);
}

// ---------------- OPTIMIZED distance + top-3 (R7 bisect swap-in) ----------------
// 128x128 output tile, 256 threads, 8x8 per thread, interleaved mapping.
// grid = (64, 2): x = I tile, y = J split. Shared-memory candidate reduction.
__global__ void __launch_bounds__(256) dist_top3_kernel() {
    __shared__ float smem[12288];           // 48 KB union buffer
    float* As = smem;                       // As[k*129 + r]
    float* Bs = smem + 32 * 129;

    const int tid = threadIdx.x;
    const int ty = tid >> 4;
    const int tx = tid & 15;
    const int i0 = blockIdx.x * 128;
    const int jbase = blockIdx.y * 4096;

    float bd[8][3];
    int   bj[8][3];
    #pragma unroll
    for (int ri = 0; ri < 8; ++ri)
        #pragma unroll
        for (int s = 0; s < 3; ++s) { bd[ri][s] = 3.0e38f; bj[ri][s] = 0x7fffffff; }

    float sqi[8];
    #pragma unroll
    for (int ri = 0; ri < 8; ++ri) sqi[ri] = g_sq[i0 + ty + 16 * ri];

    const float4* p4 = reinterpret_cast<const float4*>(g_p);

    for (int jt = 0; jt < 32; ++jt) {
        const int j0 = jbase + jt * 128;
        float acc[8][8];
        #pragma unroll
        for (int a = 0; a < 8; ++a)
            #pragma unroll
            for (int b = 0; b < 8; ++b) acc[a][b] = 0.f;

        for (int kc = 0; kc < C; kc += 32) {
            const int kc4 = kc >> 2;
            #pragma unroll
            for (int q = 0; q < 4; ++q) {
                int v = tid + 256 * q;
                int r = v >> 3;
                int c4 = v & 7;
                float4 a = p4[(size_t)(i0 + r) * 64 + kc4 + c4];
                As[(c4 * 4 + 0) * 129 + r] = a.x; As[(c4 * 4 + 1) * 129 + r] = a.y;
                As[(c4 * 4 + 2) * 129 + r] = a.z; As[(c4 * 4 + 3) * 129 + r] = a.w;
                float4 b = p4[(size_t)(j0 + r) * 64 + kc4 + c4];
                Bs[(c4 * 4 + 0) * 129 + r] = b.x; Bs[(c4 * 4 + 1) * 129 + r] = b.y;
                Bs[(c4 * 4 + 2) * 129 + r] = b.z; Bs[(c4 * 4 + 3) * 129 + r] = b.w;
            }
            __syncthreads();
            #pragma unroll
            for (int k = 0; k < 32; ++k) {
                float a[8], b[8];
                #pragma unroll
                for (int ri = 0; ri < 8; ++ri) a[ri] = As[k * 129 + ty + 16 * ri];
                #pragma unroll
                for (int ci = 0; ci < 8; ++ci) b[ci] = Bs[k * 129 + tx + 16 * ci];
                #pragma unroll
                for (int ri = 0; ri < 8; ++ri)
                    #pragma unroll
                    for (int ci = 0; ci < 8; ++ci)
                        acc[ri][ci] = fmaf(a[ri], b[ci], acc[ri][ci]);
            }
            __syncthreads();
        }

        #pragma unroll
        for (int ci = 0; ci < 8; ++ci) {
            const int j = j0 + tx + 16 * ci;
            const float sqj = g_sq[j];
            #pragma unroll
            for (int ri = 0; ri < 8; ++ri) {
                float d = sqi[ri] + sqj - 2.0f * acc[ri][ci];
                insert3(d, j, bd[ri], bj[ri]);
            }
        }
    }

    // final per-row reduction via shared memory
    __syncthreads();
    float* cd = smem;
    int*   cj = (int*)(smem + 6144);
    #pragma unroll
    for (int ri = 0; ri < 8; ++ri) {
        const int row = ty + 16 * ri;
        #pragma unroll
        for (int s = 0; s < 3; ++s) {
            cd[row * 48 + tx * 3 + s] = bd[ri][s];
            cj[row * 48 + tx * 3 + s] = bj[ri][s];
        }
    }
    __syncthreads();
    if (tid < 128) {
        const int row = tid;
        float fd[3] = {3.0e38f, 3.0e38f, 3.0e38f};
        int   fj[3] = {0x7fffffff, 0x7fffffff, 0x7fffffff};
        for (int c = 0; c < 48; ++c)
            insert3(cd[row * 48 + c], cj[row * 48 + c], fd, fj);
        const size_t base = ((size_t)blockIdx.y * N + i0 + row) * KNBR;
        #pragma unroll
        for (int s = 0; s < 3; ++s) {
            g_part_d[base + s] = fd[s];
            g_part_j[base + s] = fj[s];
        }
    }
}

// merge the 2 J-splits, apply radius mask
__global__ void merge_top3_kernel() {
    const int i = blockIdx.x * blockDim.x + threadIdx.x;
    if (i >= N) return;
    float bd[3]; int bj[3];
    #pragma unroll
    for (int s = 0; s < 3; ++s) {
        bd[s] = g_part_d[(size_t)i * KNBR + s];
        bj[s] = g_part_j[(size_t)i * KNBR + s];
    }
    #pragma unroll
    for (int s = 0; s < 3; ++s)
        insert3(g_part_d[((size_t)N + i) * KNBR + s], g_part_j[((size_t)N + i) * KNBR + s], bd, bj);
    #pragma unroll
    for (int s = 0; s < 3; ++s)
        g_idx[i * KNBR + s] = (bd[s] <= R2) ? bj[s] : -1;
}

// ---------------- neighbor aggregation (unchanged from R6) ----------------
__global__ void nv_agg() {
    int i = blockIdx.x, c2 = threadIdx.x;
    float a = 0.f;
    for (int k = 0; k < KNBR; ++k) {
        int j = g_idx[i * KNBR + k];
        if (j >= 0) a += g_h[(size_t)j * C + c2];
    }
    g_agg[(size_t)i * C + c2] = a;
}

// ---------------- x1 = relu(agg @ Wrel^T + brel + h @ Wroot^T) (unchanged) ----------------
__global__ void nv_x1(const float* __restrict__ brel, float* __restrict__ x1) {
    int i = blockIdx.x, o = threadIdx.x;
    __shared__ float as_[C], hs[C];
    as_[o] = g_agg[(size_t)i * C + o];
    hs[o]  = g_h[(size_t)i * C + o];
    __syncthreads();
    float acc = brel[o];
    for (int k = 0; k < C; ++k)
        acc += as_[k] * g_WrelT[k * C + o] + hs[k] * g_WrootT[k * C + o];
    x1[(size_t)i * C + o] = fmaxf(acc, 0.f);
}

// ---------------- out = x1 @ W2^T + b2 (unchanged from R6) ----------------
__global__ void nv_head(const float* __restrict__ x1, const float* __restrict__ W2,
                        const float* __restrict__ b2, float* __restrict__ out) {
    int i = blockIdx.x, t = threadIdx.x;
    __shared__ float xs[C];
    xs[t] = x1[(size_t)i * C + t];
    __syncthreads();
    if (t == 0) {
        for (int cls = 0; cls < NCLS; ++cls) {
            float a = b2[cls];
            for (int k = 0; k < C; ++k) a += xs[k] * W2[cls * C + k];
            out[i * NCLS + cls] = a;
        }
    }
}

// ---------------- launch ----------------
extern "C" void kernel_launch(void* const* d_in, const int* in_sizes, int n_in,
                              void* d_out, int out_size) {
    const float *x = 0, *W1 = 0, *b1 = 0, *Wrel = 0, *brel = 0, *Wroot = 0, *W2 = 0, *b2 = 0;
    int nw = 0, nb = 0;
    for (int i = 0; i < n_in; ++i) {
        const float* p = (const float*)d_in[i];
        const int s = in_sizes[i];
        if (s == N * C) x = p;
        else if (s == C * C) { if (nw == 0) W1 = p; else if (nw == 1) Wrel = p; else Wroot = p; ++nw; }
        else if (s == C) { if (nb == 0) b1 = p; else brel = p; ++nb; }
        else if (s == NCLS * C) W2 = p;
        else if (s == NCLS) b2 = p;
    }

    float *x1dst, *outdst;
    float *x1_scr, *out_scr;
    cudaGetSymbolAddress((void**)&x1_scr, g_x1s);
    cudaGetSymbolAddress((void**)&out_scr, g_outs);
    if (out_size >= N * NCLS + N * C) {
        outdst = (float*)d_out;
        x1dst  = outdst + (size_t)N * NCLS;
    } else if (out_size == N * C) {
        x1dst  = (float*)d_out;
        outdst = out_scr;
    } else {
        outdst = (float*)d_out;
        x1dst  = x1_scr;
    }

    float *w1t, *wrelt, *wroott;
    cudaGetSymbolAddress((void**)&w1t, g_W1T);
    cudaGetSymbolAddress((void**)&wrelt, g_WrelT);
    cudaGetSymbolAddress((void**)&wroott, g_WrootT);

    nv_transpose<<<C, C>>>(W1, w1t);
    nv_transpose<<<C, C>>>(Wrel, wrelt);
    nv_transpose<<<C, C>>>(Wroot, wroott);
    nv_softmax<<<N, C>>>(x);
    nv_h<<<N, C>>>(x, b1);
    dist_top3_kernel<<<dim3(N / 128, 2), 256>>>();
    merge_top3_kernel<<<N / 256, 256>>>();
    nv_agg<<<N, C>>>();
    nv_x1<<<N, C>>>(brel, x1dst);
    nv_head<<<N, C>>>(x1dst, W2, b2, outdst);
}

// round 10
// speedup vs baseline: 3.4614x; 1.1138x over previous
#include <cuda_runtime.h>
#include <math.h>
#include <limits.h>

#define N 8192
#define C 256
#define NCLS 2
#define KNBR 3
#define R2 9.0f

// ---------------- device scratch ----------------
__device__ float g_p[N * C];
__device__ float g_sq[N];
__device__ float g_h[N * C];
__device__ float g_agg[N * C];
__device__ float g_x1s[N * C];
__device__ float g_outs[N * NCLS];
__device__ int   g_idx[N * KNBR];
__device__ float g_W1T[C * C];
__device__ float g_WrelT[C * C];
__device__ float g_WrootT[C * C];
__device__ float g_part_d[2 * N * KNBR];
__device__ int   g_part_j[2 * N * KNBR];

// ---------------- packed f32x2 helpers (sm_103a FFMA2) ----------------
__device__ __forceinline__ unsigned long long pack2(float lo, float hi) {
    unsigned long long r;
    asm("mov.b64 %0, {%1, %2};" : "=l"(r) : "f"(lo), "f"(hi));
    return r;
}
__device__ __forceinline__ void fma2(unsigned long long& d,
                                     unsigned long long a,
                                     unsigned long long b) {
    asm("fma.rn.f32x2 %0, %1, %2, %3;" : "=l"(d) : "l"(a), "l"(b), "l"(d));
}
__device__ __forceinline__ float2 unpack2(unsigned long long v) {
    float2 f;
    asm("mov.b64 {%0, %1}, %2;" : "=f"(f.x), "=f"(f.y) : "l"(v));
    return f;
}

// ---------------- helpers ----------------
__device__ __forceinline__ void insert3(float d, int j, float bd[3], int bj[3]) {
    bool l2 = (d < bd[2]) || (d == bd[2] && j < bj[2]);
    if (!l2) return;
    bool l1 = (d < bd[1]) || (d == bd[1] && j < bj[1]);
    bool l0 = (d < bd[0]) || (d == bd[0] && j < bj[0]);
    if (l0) {
        bd[2] = bd[1]; bj[2] = bj[1];
        bd[1] = bd[0]; bj[1] = bj[0];
        bd[0] = d;     bj[0] = j;
    } else if (l1) {
        bd[2] = bd[1]; bj[2] = bj[1];
        bd[1] = d;     bj[1] = j;
    } else {
        bd[2] = d;     bj[2] = j;
    }
}

// ---------------- transpose (R7-proven) ----------------
__global__ void nv_transpose(const float* __restrict__ W, float* __restrict__ WT) {
    int o = blockIdx.x;
    int k = threadIdx.x;
    WT[k * C + o] = W[o * C + k];
}

// ---------------- softmax + sq norms (R7-proven) ----------------
__global__ void nv_softmax(const float* __restrict__ x) {
    int i = blockIdx.x;
    int t = threadIdx.x;
    __shared__ float row[C];
    row[t] = x[i * C + t];
    __syncthreads();
    if (t == 0) {
        float m = row[0];
        for (int k = 1; k < C; ++k) m = fmaxf(m, row[k]);
        float s = 0.f;
        for (int k = 0; k < C; ++k) { row[k] = expf(row[k] - m); s += row[k]; }
        float sq = 0.f;
        for (int k = 0; k < C; ++k) {
            float p = row[k] / s;
            g_p[i * C + k] = p;
            sq += p * p;
        }
        g_sq[i] = sq;
    }
}

// ---------------- h = relu(x @ W1^T + b1) (R7-proven) ----------------
__global__ void nv_h(const float* __restrict__ x, const float* __restrict__ b1) {
    int i = blockIdx.x, o = threadIdx.x;
    __shared__ float xs[C];
    xs[o] = x[i * C + o];
    __syncthreads();
    float acc = b1[o];
    for (int k = 0; k < C; ++k) acc += xs[k] * g_W1T[k * C + o];
    g_h[i * C + o] = fmaxf(acc, 0.f);
}

// ---------------- distance + top-3, FFMA2 inner loop ----------------
__global__ void __launch_bounds__(256) dist_top3_kernel() {
    __shared__ float smem[12288];
    float* As = smem;
    float* Bs = smem + 32 * 129;

    const int tid = threadIdx.x;
    const int ty = tid >> 4;
    const int tx = tid & 15;
    const int i0 = blockIdx.x * 128;
    const int jbase = blockIdx.y * 4096;

    float bd[8][3];
    int   bj[8][3];
    #pragma unroll
    for (int ri = 0; ri < 8; ++ri)
        #pragma unroll
        for (int s = 0; s < 3; ++s) { bd[ri][s] = 3.0e38f; bj[ri][s] = 0x7fffffff; }

    float sqi[8];
    #pragma unroll
    for (int ri = 0; ri < 8; ++ri) sqi[ri] = g_sq[i0 + ty + 16 * ri];

    const float4* p4 = reinterpret_cast<const float4*>(g_p);

    for (int jt = 0; jt < 32; ++jt) {
        const int j0 = jbase + jt * 128;

        unsigned long long acc2[8][4];   // packed pairs: (ci=2c2, ci=2c2+1)
        #pragma unroll
        for (int ri = 0; ri < 8; ++ri)
            #pragma unroll
            for (int c2 = 0; c2 < 4; ++c2) acc2[ri][c2] = 0ull;  // (0.f, 0.f)

        for (int kc = 0; kc < C; kc += 32) {
            const int kc4 = kc >> 2;
            #pragma unroll
            for (int q = 0; q < 4; ++q) {
                int v = tid + 256 * q;
                int r = v >> 3;
                int c4 = v & 7;
                float4 a = p4[(size_t)(i0 + r) * 64 + kc4 + c4];
                As[(c4 * 4 + 0) * 129 + r] = a.x; As[(c4 * 4 + 1) * 129 + r] = a.y;
                As[(c4 * 4 + 2) * 129 + r] = a.z; As[(c4 * 4 + 3) * 129 + r] = a.w;
                float4 b = p4[(size_t)(j0 + r) * 64 + kc4 + c4];
                Bs[(c4 * 4 + 0) * 129 + r] = b.x; Bs[(c4 * 4 + 1) * 129 + r] = b.y;
                Bs[(c4 * 4 + 2) * 129 + r] = b.z; Bs[(c4 * 4 + 3) * 129 + r] = b.w;
            }
            __syncthreads();
            #pragma unroll
            for (int k = 0; k < 32; ++k) {
                float a_s[8], b_s[8];
                #pragma unroll
                for (int ri = 0; ri < 8; ++ri) a_s[ri] = As[k * 129 + ty + 16 * ri];
                #pragma unroll
                for (int ci = 0; ci < 8; ++ci) b_s[ci] = Bs[k * 129 + tx + 16 * ci];
                unsigned long long bb[4];
                #pragma unroll
                for (int c2 = 0; c2 < 4; ++c2) bb[c2] = pack2(b_s[2 * c2], b_s[2 * c2 + 1]);
                #pragma unroll
                for (int ri = 0; ri < 8; ++ri) {
                    unsigned long long aa = pack2(a_s[ri], a_s[ri]);
                    #pragma unroll
                    for (int c2 = 0; c2 < 4; ++c2)
                        fma2(acc2[ri][c2], aa, bb[c2]);
                }
            }
            __syncthreads();
        }

        // epilogue: unpack pairs; iterate ci ascending (same tie order as before)
        #pragma unroll
        for (int c2 = 0; c2 < 4; ++c2) {
            #pragma unroll
            for (int half = 0; half < 2; ++half) {
                const int ci = 2 * c2 + half;
                const int j = j0 + tx + 16 * ci;
                const float sqj = g_sq[j];
                #pragma unroll
                for (int ri = 0; ri < 8; ++ri) {
                    float2 u = unpack2(acc2[ri][c2]);
                    float dot = half ? u.y : u.x;
                    float d = sqi[ri] + sqj - 2.0f * dot;
                    insert3(d, j, bd[ri], bj[ri]);
                }
            }
        }
    }

    __syncthreads();
    float* cd = smem;
    int*   cj = (int*)(smem + 6144);
    #pragma unroll
    for (int ri = 0; ri < 8; ++ri) {
        const int row = ty + 16 * ri;
        #pragma unroll
        for (int s = 0; s < 3; ++s) {
            cd[row * 48 + tx * 3 + s] = bd[ri][s];
            cj[row * 48 + tx * 3 + s] = bj[ri][s];
        }
    }
    __syncthreads();
    if (tid < 128) {
        const int row = tid;
        float fd[3] = {3.0e38f, 3.0e38f, 3.0e38f};
        int   fj[3] = {0x7fffffff, 0x7fffffff, 0x7fffffff};
        for (int c = 0; c < 48; ++c)
            insert3(cd[row * 48 + c], cj[row * 48 + c], fd, fj);
        const size_t base = ((size_t)blockIdx.y * N + i0 + row) * KNBR;
        #pragma unroll
        for (int s = 0; s < 3; ++s) {
            g_part_d[base + s] = fd[s];
            g_part_j[base + s] = fj[s];
        }
    }
}

__global__ void merge_top3_kernel() {
    const int i = blockIdx.x * blockDim.x + threadIdx.x;
    if (i >= N) return;
    float bd[3]; int bj[3];
    #pragma unroll
    for (int s = 0; s < 3; ++s) {
        bd[s] = g_part_d[(size_t)i * KNBR + s];
        bj[s] = g_part_j[(size_t)i * KNBR + s];
    }
    #pragma unroll
    for (int s = 0; s < 3; ++s)
        insert3(g_part_d[((size_t)N + i) * KNBR + s], g_part_j[((size_t)N + i) * KNBR + s], bd, bj);
    #pragma unroll
    for (int s = 0; s < 3; ++s)
        g_idx[i * KNBR + s] = (bd[s] <= R2) ? bj[s] : -1;
}

// ---------------- neighbor aggregation (R7-proven) ----------------
__global__ void nv_agg() {
    int i = blockIdx.x, c2 = threadIdx.x;
    float a = 0.f;
    for (int k = 0; k < KNBR; ++k) {
        int j = g_idx[i * KNBR + k];
        if (j >= 0) a += g_h[(size_t)j * C + c2];
    }
    g_agg[(size_t)i * C + c2] = a;
}

// ---------------- x1 = relu(agg @ Wrel^T + brel + h @ Wroot^T) (R7-proven) ----------------
__global__ void nv_x1(const float* __restrict__ brel, float* __restrict__ x1) {
    int i = blockIdx.x, o = threadIdx.x;
    __shared__ float as_[C], hs[C];
    as_[o] = g_agg[(size_t)i * C + o];
    hs[o]  = g_h[(size_t)i * C + o];
    __syncthreads();
    float acc = brel[o];
    for (int k = 0; k < C; ++k)
        acc += as_[k] * g_WrelT[k * C + o] + hs[k] * g_WrootT[k * C + o];
    x1[(size_t)i * C + o] = fmaxf(acc, 0.f);
}

// ---------------- out = x1 @ W2^T + b2 (R7-proven) ----------------
__global__ void nv_head(const float* __restrict__ x1, const float* __restrict__ W2,
                        const float* __restrict__ b2, float* __restrict__ out) {
    int i = blockIdx.x, t = threadIdx.x;
    __shared__ float xs[C];
    xs[t] = x1[(size_t)i * C + t];
    __syncthreads();
    if (t == 0) {
        for (int cls = 0; cls < NCLS; ++cls) {
            float a = b2[cls];
            for (int k = 0; k < C; ++k) a += xs[k] * W2[cls * C + k];
            out[i * NCLS + cls] = a;
        }
    }
}

// ---------------- launch ----------------
extern "C" void kernel_launch(void* const* d_in, const int* in_sizes, int n_in,
                              void* d_out, int out_size) {
    const float *x = 0, *W1 = 0, *b1 = 0, *Wrel = 0, *brel = 0, *Wroot = 0, *W2 = 0, *b2 = 0;
    int nw = 0, nb = 0;
    for (int i = 0; i < n_in; ++i) {
        const float* p = (const float*)d_in[i];
        const int s = in_sizes[i];
        if (s == N * C) x = p;
        else if (s == C * C) { if (nw == 0) W1 = p; else if (nw == 1) Wrel = p; else Wroot = p; ++nw; }
        else if (s == C) { if (nb == 0) b1 = p; else brel = p; ++nb; }
        else if (s == NCLS * C) W2 = p;
        else if (s == NCLS) b2 = p;
    }

    float *x1dst, *outdst;
    float *x1_scr, *out_scr;
    cudaGetSymbolAddress((void**)&x1_scr, g_x1s);
    cudaGetSymbolAddress((void**)&out_scr, g_outs);
    if (out_size >= N * NCLS + N * C) {
        outdst = (float*)d_out;
        x1dst  = outdst + (size_t)N * NCLS;
    } else if (out_size == N * C) {
        x1dst  = (float*)d_out;
        outdst = out_scr;
    } else {
        outdst = (float*)d_out;
        x1dst  = x1_scr;
    }

    float *w1t, *wrelt, *wroott;
    cudaGetSymbolAddress((void**)&w1t, g_W1T);
    cudaGetSymbolAddress((void**)&wrelt, g_WrelT);
    cudaGetSymbolAddress((void**)&wroott, g_WrootT);

    nv_transpose<<<C, C>>>(W1, w1t);
    nv_transpose<<<C, C>>>(Wrel, wrelt);
    nv_transpose<<<C, C>>>(Wroot, wroott);
    nv_softmax<<<N, C>>>(x);
    nv_h<<<N, C>>>(x, b1);
    dist_top3_kernel<<<dim3(N / 128, 2), 256>>>();
    merge_top3_kernel<<<N / 256, 256>>>();
    nv_agg<<<N, C>>>();
    nv_x1<<<N, C>>>(brel, x1dst);
    nv_head<<<N, C>>>(x1dst, W2, b2, outdst);
}

// round 14
// speedup vs baseline: 4.0762x; 1.1776x over previous
#include <cuda_runtime.h>
#include <math.h>
#include <limits.h>
#include <stdint.h>

#define N 8192
#define C 256
#define NCLS 2
#define KNBR 3
#define KCAND 6          // candidates kept per row per j-split
#define R2 9.0f

#define KC 64            // k-chunk
#define ASTR 68          // smem row stride (floats): conflict-free frag loads
#define PLANE (128 * ASTR)
#define SM_DIST_BYTES (4 * PLANE * 4)   // 4 planes of fp32 = 139,264 B

// ---------------- device scratch ----------------
__device__ float g_p[N * C];
__device__ float g_hi[N * C];
__device__ float g_lo[N * C];
__device__ float g_sq[N];
__device__ float g_h[N * C];
__device__ float g_agg[N * C];
__device__ float g_x1s[N * C];
__device__ float g_outs[N * NCLS];
__device__ int   g_idx[N * KNBR];
__device__ float g_W1T[C * C];
__device__ float g_WrelT[C * C];
__device__ float g_WrootT[C * C];
__device__ float g_part_d[2 * N * KCAND];
__device__ int   g_part_j[2 * N * KCAND];

// ---------------- helpers ----------------
__device__ __forceinline__ void insert3(float d, int j, float bd[3], int bj[3]) {
    bool l2 = (d < bd[2]) || (d == bd[2] && j < bj[2]);
    if (!l2) return;
    bool l1 = (d < bd[1]) || (d == bd[1] && j < bj[1]);
    bool l0 = (d < bd[0]) || (d == bd[0] && j < bj[0]);
    if (l0) {
        bd[2] = bd[1]; bj[2] = bj[1];
        bd[1] = bd[0]; bj[1] = bj[0];
        bd[0] = d;     bj[0] = j;
    } else if (l1) {
        bd[2] = bd[1]; bj[2] = bj[1];
        bd[1] = d;     bj[1] = j;
    } else {
        bd[2] = d;     bj[2] = j;
    }
}

// sorted insertion into a K-long (d,j) list, lexicographic (d, j)
__device__ __forceinline__ void insertK(float d, int j, float* bd, int* bj, int K) {
    if (!((d < bd[K - 1]) || (d == bd[K - 1] && j < bj[K - 1]))) return;
    bd[K - 1] = d; bj[K - 1] = j;
    for (int s = K - 1; s > 0; --s) {
        bool sw = (bd[s] < bd[s - 1]) || (bd[s] == bd[s - 1] && bj[s] < bj[s - 1]);
        if (!sw) break;
        float td = bd[s]; bd[s] = bd[s - 1]; bd[s - 1] = td;
        int tj = bj[s]; bj[s] = bj[s - 1]; bj[s - 1] = tj;
    }
}

__device__ __forceinline__ void mma_tf32(float* c, const uint32_t* a, const uint32_t* b) {
    asm volatile(
        "mma.sync.aligned.m16n8k8.row.col.f32.tf32.tf32.f32 "
        "{%0,%1,%2,%3}, {%4,%5,%6,%7}, {%8,%9}, {%0,%1,%2,%3};"
        : "+f"(c[0]), "+f"(c[1]), "+f"(c[2]), "+f"(c[3])
        : "r"(a[0]), "r"(a[1]), "r"(a[2]), "r"(a[3]), "r"(b[0]), "r"(b[1]));
}

// ---------------- softmax + sq norms (proven) ----------------
__global__ void nv_softmax(const float* __restrict__ x) {
    int i = blockIdx.x;
    int t = threadIdx.x;
    __shared__ float row[C];
    row[t] = x[i * C + t];
    __syncthreads();
    if (t == 0) {
        float m = row[0];
        for (int k = 1; k < C; ++k) m = fmaxf(m, row[k]);
        float s = 0.f;
        for (int k = 0; k < C; ++k) { row[k] = expf(row[k] - m); s += row[k]; }
        float sq = 0.f;
        for (int k = 0; k < C; ++k) {
            float p = row[k] / s;
            g_p[i * C + k] = p;
            sq += p * p;
        }
        g_sq[i] = sq;
    }
}

// ---------------- split p -> tf32 hi + lo ----------------
__global__ void split_tf32_kernel() {
    const int i = blockIdx.x;
    const int k = threadIdx.x;
    float p = g_p[i * C + k];
    uint32_t hb;
    asm("cvt.rna.tf32.f32 %0, %1;" : "=r"(hb) : "f"(p));
    float hf = __uint_as_float(hb);
    float lf = p - hf;
    uint32_t lb;
    asm("cvt.rna.tf32.f32 %0, %1;" : "=r"(lb) : "f"(lf));
    g_hi[i * C + k] = hf;
    g_lo[i * C + k] = __uint_as_float(lb);
}

// ---------------- tensor-core (3xTF32) candidate generation ----------------
// grid (64, 2): x = i-tile of 128 rows; y = j-split. Outputs top-6 per row per split.
__global__ void __launch_bounds__(256) dist_tc32_kernel() {
    extern __shared__ float smem[];
    float* Ah = smem;
    float* Al = smem + PLANE;
    float* Bh = smem + 2 * PLANE;
    float* Bl = smem + 3 * PLANE;

    const int tid = threadIdx.x;
    const int wid = tid >> 5, lane = tid & 31;
    const int warp_m = wid & 3, warp_n = wid >> 2;
    const int qr = lane >> 2, tq = lane & 3;
    const int i0 = blockIdx.x * 128;
    const int jbase = blockIdx.y * 4096;

    float sqi[4];
    #pragma unroll
    for (int mf = 0; mf < 2; ++mf)
        #pragma unroll
        for (int hf = 0; hf < 2; ++hf)
            sqi[mf * 2 + hf] = g_sq[i0 + warp_m * 32 + mf * 16 + 8 * hf + qr];

    float bd[4][3];
    int   bj[4][3];
    #pragma unroll
    for (int r = 0; r < 4; ++r)
        #pragma unroll
        for (int s = 0; s < 3; ++s) { bd[r][s] = 3.0e38f; bj[r][s] = INT_MAX; }

    const float4* hi4 = reinterpret_cast<const float4*>(g_hi);
    const float4* lo4 = reinterpret_cast<const float4*>(g_lo);

    for (int jt = 0; jt < 32; ++jt) {
        const int j0 = jbase + jt * 128;

        float acc[2][8][4];
        #pragma unroll
        for (int mf = 0; mf < 2; ++mf)
            #pragma unroll
            for (int nf = 0; nf < 8; ++nf)
                #pragma unroll
                for (int s = 0; s < 4; ++s) acc[mf][nf][s] = 0.f;

        for (int kc = 0; kc < C; kc += KC) {
            const int kq = kc >> 2;
            #pragma unroll
            for (int q = 0; q < 8; ++q) {
                int e = tid + 256 * q;
                int r = e >> 4, c4 = e & 15;
                float4 va = hi4[(size_t)(i0 + r) * 64 + kq + c4];
                *reinterpret_cast<float4*>(Ah + r * ASTR + 4 * c4) = va;
                float4 vb = lo4[(size_t)(i0 + r) * 64 + kq + c4];
                *reinterpret_cast<float4*>(Al + r * ASTR + 4 * c4) = vb;
                float4 vc = hi4[(size_t)(j0 + r) * 64 + kq + c4];
                *reinterpret_cast<float4*>(Bh + r * ASTR + 4 * c4) = vc;
                float4 vd = lo4[(size_t)(j0 + r) * 64 + kq + c4];
                *reinterpret_cast<float4*>(Bl + r * ASTR + 4 * c4) = vd;
            }
            __syncthreads();

            #pragma unroll
            for (int ks = 0; ks < KC / 8; ++ks) {
                const int k0 = ks * 8;
                uint32_t ah[2][4], al[2][4];
                #pragma unroll
                for (int mf = 0; mf < 2; ++mf) {
                    const int r0 = (warp_m * 32 + mf * 16 + qr) * ASTR;
                    ah[mf][0] = __float_as_uint(Ah[r0 + k0 + tq]);
                    ah[mf][1] = __float_as_uint(Ah[r0 + 8 * ASTR + k0 + tq]);
                    ah[mf][2] = __float_as_uint(Ah[r0 + k0 + 4 + tq]);
                    ah[mf][3] = __float_as_uint(Ah[r0 + 8 * ASTR + k0 + 4 + tq]);
                    al[mf][0] = __float_as_uint(Al[r0 + k0 + tq]);
                    al[mf][1] = __float_as_uint(Al[r0 + 8 * ASTR + k0 + tq]);
                    al[mf][2] = __float_as_uint(Al[r0 + k0 + 4 + tq]);
                    al[mf][3] = __float_as_uint(Al[r0 + 8 * ASTR + k0 + 4 + tq]);
                }
                uint32_t bh[8][2], bl[8][2];
                #pragma unroll
                for (int nf = 0; nf < 8; ++nf) {
                    const int c0 = (warp_n * 64 + nf * 8 + qr) * ASTR;
                    bh[nf][0] = __float_as_uint(Bh[c0 + k0 + tq]);
                    bh[nf][1] = __float_as_uint(Bh[c0 + k0 + 4 + tq]);
                    bl[nf][0] = __float_as_uint(Bl[c0 + k0 + tq]);
                    bl[nf][1] = __float_as_uint(Bl[c0 + k0 + 4 + tq]);
                }
                #pragma unroll
                for (int mf = 0; mf < 2; ++mf)
                    #pragma unroll
                    for (int nf = 0; nf < 8; ++nf) {
                        mma_tf32(acc[mf][nf], ah[mf], bh[nf]);  // hi*hi
                        mma_tf32(acc[mf][nf], ah[mf], bl[nf]);  // hi*lo
                        mma_tf32(acc[mf][nf], al[mf], bh[nf]);  // lo*hi
                    }
            }
            __syncthreads();
        }

        #pragma unroll
        for (int mf = 0; mf < 2; ++mf)
            #pragma unroll
            for (int nf = 0; nf < 8; ++nf)
                #pragma unroll
                for (int s = 0; s < 4; ++s) {
                    const int hf = s >> 1;
                    const int col = warp_n * 64 + nf * 8 + 2 * tq + (s & 1);
                    const int j = j0 + col;
                    const float d = sqi[mf * 2 + hf] + g_sq[j] - 2.0f * acc[mf][nf][s];
                    insert3(d, j, bd[mf * 2 + hf], bj[mf * 2 + hf]);
                }
    }

    // row-level reduction: 24 contributor candidates -> top-6 (MMA metric)
    __syncthreads();
    float* cd = smem;                              // 128*24 floats
    int*   cj = reinterpret_cast<int*>(smem + 128 * 24);
    const int contrib = tq + 4 * warp_n;           // 0..7
    #pragma unroll
    for (int mf = 0; mf < 2; ++mf)
        #pragma unroll
        for (int hf = 0; hf < 2; ++hf) {
            const int row = warp_m * 32 + mf * 16 + 8 * hf + qr;
            #pragma unroll
            for (int s = 0; s < 3; ++s) {
                cd[row * 24 + contrib * 3 + s] = bd[mf * 2 + hf][s];
                cj[row * 24 + contrib * 3 + s] = bj[mf * 2 + hf][s];
            }
        }
    __syncthreads();
    if (tid < 128) {
        float fd[KCAND];
        int   fj[KCAND];
        #pragma unroll
        for (int s = 0; s < KCAND; ++s) { fd[s] = 3.0e38f; fj[s] = INT_MAX; }
        for (int c = 0; c < 24; ++c)
            insertK(cd[tid * 24 + c], cj[tid * 24 + c], fd, fj, KCAND);
        const size_t base = ((size_t)blockIdx.y * N + i0 + tid) * KCAND;
        #pragma unroll
        for (int s = 0; s < KCAND; ++s) {
            g_part_d[base + s] = fd[s];
            g_part_j[base + s] = fj[s];
        }
    }
}

// ---------------- exact fp32 rescore + final top-3 ----------------
// warp per row: 12 candidates re-scored with exact fp32 dot over g_p.
__global__ void __launch_bounds__(256) rescore_kernel() {
    const int tid = threadIdx.x;
    const int wid = tid >> 5, lane = tid & 31;
    const int i = blockIdx.x * 8 + wid;

    // cache my slice of row i
    float pi[8];
    #pragma unroll
    for (int q = 0; q < 8; ++q) pi[q] = g_p[(size_t)i * C + lane + 32 * q];
    const float sqi = g_sq[i];

    float bd[3] = {3.0e38f, 3.0e38f, 3.0e38f};
    int   bj[3] = {INT_MAX, INT_MAX, INT_MAX};

    for (int sp = 0; sp < 2; ++sp) {
        #pragma unroll
        for (int s = 0; s < KCAND; ++s) {
            const int j = g_part_j[((size_t)sp * N + i) * KCAND + s];
            float a = 0.f;
            #pragma unroll
            for (int q = 0; q < 8; ++q)
                a = fmaf(pi[q], g_p[(size_t)j * C + lane + 32 * q], a);
            #pragma unroll
            for (int off = 16; off; off >>= 1)
                a += __shfl_xor_sync(~0u, a, off);
            const float d = sqi + g_sq[j] - 2.0f * a;
            insert3(d, j, bd, bj);
        }
    }

    if (lane == 0) {
        #pragma unroll
        for (int s = 0; s < 3; ++s)
            g_idx[i * KNBR + s] = (bd[s] <= R2) ? bj[s] : -1;
    }
}

// ---------------- tail (all proven) ----------------
__global__ void nv_transpose(const float* __restrict__ W, float* __restrict__ WT) {
    int o = blockIdx.x;
    int k = threadIdx.x;
    WT[k * C + o] = W[o * C + k];
}

__global__ void nv_h(const float* __restrict__ x, const float* __restrict__ b1) {
    int i = blockIdx.x, o = threadIdx.x;
    __shared__ float xs[C];
    xs[o] = x[i * C + o];
    __syncthreads();
    float acc = b1[o];
    for (int k = 0; k < C; ++k) acc += xs[k] * g_W1T[k * C + o];
    g_h[i * C + o] = fmaxf(acc, 0.f);
}

__global__ void nv_agg() {
    int i = blockIdx.x, c2 = threadIdx.x;
    float a = 0.f;
    for (int k = 0; k < KNBR; ++k) {
        int j = g_idx[i * KNBR + k];
        if (j >= 0) a += g_h[(size_t)j * C + c2];
    }
    g_agg[(size_t)i * C + c2] = a;
}

__global__ void nv_x1(const float* __restrict__ brel, float* __restrict__ x1) {
    int i = blockIdx.x, o = threadIdx.x;
    __shared__ float as_[C], hs[C];
    as_[o] = g_agg[(size_t)i * C + o];
    hs[o]  = g_h[(size_t)i * C + o];
    __syncthreads();
    float acc = brel[o];
    for (int k = 0; k < C; ++k)
        acc += as_[k] * g_WrelT[k * C + o] + hs[k] * g_WrootT[k * C + o];
    x1[(size_t)i * C + o] = fmaxf(acc, 0.f);
}

__global__ void nv_head(const float* __restrict__ x1, const float* __restrict__ W2,
                        const float* __restrict__ b2, float* __restrict__ out) {
    int i = blockIdx.x, t = threadIdx.x;
    __shared__ float xs[C];
    xs[t] = x1[(size_t)i * C + t];
    __syncthreads();
    if (t == 0) {
        for (int cls = 0; cls < NCLS; ++cls) {
            float a = b2[cls];
            for (int k = 0; k < C; ++k) a += xs[k] * W2[cls * C + k];
            out[i * NCLS + cls] = a;
        }
    }
}

// ---------------- launch ----------------
extern "C" void kernel_launch(void* const* d_in, const int* in_sizes, int n_in,
                              void* d_out, int out_size) {
    const float *x = 0, *W1 = 0, *b1 = 0, *Wrel = 0, *brel = 0, *Wroot = 0, *W2 = 0, *b2 = 0;
    int nw = 0, nb = 0;
    for (int i = 0; i < n_in; ++i) {
        const float* p = (const float*)d_in[i];
        const int s = in_sizes[i];
        if (s == N * C) x = p;
        else if (s == C * C) { if (nw == 0) W1 = p; else if (nw == 1) Wrel = p; else Wroot = p; ++nw; }
        else if (s == C) { if (nb == 0) b1 = p; else brel = p; ++nb; }
        else if (s == NCLS * C) W2 = p;
        else if (s == NCLS) b2 = p;
    }

    float *x1dst, *outdst;
    float *x1_scr, *out_scr;
    cudaGetSymbolAddress((void**)&x1_scr, g_x1s);
    cudaGetSymbolAddress((void**)&out_scr, g_outs);
    if (out_size >= N * NCLS + N * C) {
        outdst = (float*)d_out;
        x1dst  = outdst + (size_t)N * NCLS;
    } else if (out_size == N * C) {
        x1dst  = (float*)d_out;
        outdst = out_scr;
    } else {
        outdst = (float*)d_out;
        x1dst  = x1_scr;
    }

    float *w1t, *wrelt, *wroott;
    cudaGetSymbolAddress((void**)&w1t, g_W1T);
    cudaGetSymbolAddress((void**)&wrelt, g_WrelT);
    cudaGetSymbolAddress((void**)&wroott, g_WrootT);

    cudaFuncSetAttribute(dist_tc32_kernel,
                         cudaFuncAttributeMaxDynamicSharedMemorySize, SM_DIST_BYTES);

    nv_transpose<<<C, C>>>(W1, w1t);
    nv_transpose<<<C, C>>>(Wrel, wrelt);
    nv_transpose<<<C, C>>>(Wroot, wroott);
    nv_softmax<<<N, C>>>(x);
    split_tf32_kernel<<<N, C>>>();
    nv_h<<<N, C>>>(x, b1);
    dist_tc32_kernel<<<dim3(N / 128, 2), 256, SM_DIST_BYTES>>>();
    rescore_kernel<<<N / 8, 256>>>();
    nv_agg<<<N, C>>>();
    nv_x1<<<N, C>>>(brel, x1dst);
    nv_head<<<N, C>>>(x1dst, W2, b2, outdst);
}

// round 16
// speedup vs baseline: 4.4461x; 1.0908x over previous
#include <cuda_runtime.h>
#include <math.h>
#include <limits.h>
#include <stdint.h>

#define N 8192
#define C 256
#define NCLS 2
#define KNBR 3
#define KCAND 6
#define R2 9.0f

#define KC 64
#define ASTR 68
#define PLANE (128 * ASTR)
#define SM_DIST_BYTES (4 * PLANE * 4)

__device__ float g_p[N * C];
__device__ float g_hi[N * C];
__device__ float g_lo[N * C];
__device__ float g_sq[N];
__device__ float g_h[N * C];
__device__ float g_agg[N * C];
__device__ float g_x1s[N * C];
__device__ float g_outs[N * NCLS];
__device__ int   g_idx[N * KNBR];
__device__ float g_W1T[C * C];
__device__ float g_WrelT[C * C];
__device__ float g_WrootT[C * C];
__device__ float g_part_d[2 * N * KCAND];
__device__ int   g_part_j[2 * N * KCAND];

__device__ __forceinline__ void insert3(float d, int j, float bd[3], int bj[3]) {
    bool l2 = (d < bd[2]) || (d == bd[2] && j < bj[2]);
    if (!l2) return;
    bool l1 = (d < bd[1]) || (d == bd[1] && j < bj[1]);
    bool l0 = (d < bd[0]) || (d == bd[0] && j < bj[0]);
    if (l0) {
        bd[2] = bd[1]; bj[2] = bj[1];
        bd[1] = bd[0]; bj[1] = bj[0];
        bd[0] = d;     bj[0] = j;
    } else if (l1) {
        bd[2] = bd[1]; bj[2] = bj[1];
        bd[1] = d;     bj[1] = j;
    } else {
        bd[2] = d;     bj[2] = j;
    }
}

__device__ __forceinline__ void insertK(float d, int j, float* bd, int* bj, int K) {
    if (!((d < bd[K - 1]) || (d == bd[K - 1] && j < bj[K - 1]))) return;
    bd[K - 1] = d; bj[K - 1] = j;
    for (int s = K - 1; s > 0; --s) {
        bool sw = (bd[s] < bd[s - 1]) || (bd[s] == bd[s - 1] && bj[s] < bj[s - 1]);
        if (!sw) break;
        float td = bd[s]; bd[s] = bd[s - 1]; bd[s - 1] = td;
        int tj = bj[s]; bj[s] = bj[s - 1]; bj[s - 1] = tj;
    }
}

__device__ __forceinline__ void mma_tf32(float* c, const uint32_t* a, const uint32_t* b) {
    asm volatile(
        "mma.sync.aligned.m16n8k8.row.col.f32.tf32.tf32.f32 "
        "{%0,%1,%2,%3}, {%4,%5,%6,%7}, {%8,%9}, {%0,%1,%2,%3};"
        : "+f"(c[0]), "+f"(c[1]), "+f"(c[2]), "+f"(c[3])
        : "r"(a[0]), "r"(a[1]), "r"(a[2]), "r"(a[3]), "r"(b[0]), "r"(b[1]));
}

// ---------------- softmax + sq norms (proven) ----------------
__global__ void nv_softmax(const float* __restrict__ x) {
    int i = blockIdx.x;
    int t = threadIdx.x;
    __shared__ float row[C];
    row[t] = x[i * C + t];
    __syncthreads();
    if (t == 0) {
        float m = row[0];
        for (int k = 1; k < C; ++k) m = fmaxf(m, row[k]);
        float s = 0.f;
        for (int k = 0; k < C; ++k) { row[k] = expf(row[k] - m); s += row[k]; }
        float sq = 0.f;
        for (int k = 0; k < C; ++k) {
            float p = row[k] / s;
            g_p[i * C + k] = p;
            sq += p * p;
        }
        g_sq[i] = sq;
    }
}

// ---------------- split p -> tf32 hi + lo (proven R14) ----------------
__global__ void split_tf32_kernel() {
    const int i = blockIdx.x;
    const int k = threadIdx.x;
    float p = g_p[i * C + k];
    uint32_t hb;
    asm("cvt.rna.tf32.f32 %0, %1;" : "=r"(hb) : "f"(p));
    float hf = __uint_as_float(hb);
    float lf = p - hf;
    uint32_t lb;
    asm("cvt.rna.tf32.f32 %0, %1;" : "=r"(lb) : "f"(lf));
    g_hi[i * C + k] = hf;
    g_lo[i * C + k] = __uint_as_float(lb);
}

// ---------------- 3xTF32 candidate generation (proven R14, verbatim) ----------------
__global__ void __launch_bounds__(256) dist_tc32_kernel() {
    extern __shared__ float smem[];
    float* Ah = smem;
    float* Al = smem + PLANE;
    float* Bh = smem + 2 * PLANE;
    float* Bl = smem + 3 * PLANE;

    const int tid = threadIdx.x;
    const int wid = tid >> 5, lane = tid & 31;
    const int warp_m = wid & 3, warp_n = wid >> 2;
    const int qr = lane >> 2, tq = lane & 3;
    const int i0 = blockIdx.x * 128;
    const int jbase = blockIdx.y * 4096;

    float sqi[4];
    #pragma unroll
    for (int mf = 0; mf < 2; ++mf)
        #pragma unroll
        for (int hf = 0; hf < 2; ++hf)
            sqi[mf * 2 + hf] = g_sq[i0 + warp_m * 32 + mf * 16 + 8 * hf + qr];

    float bd[4][3];
    int   bj[4][3];
    #pragma unroll
    for (int r = 0; r < 4; ++r)
        #pragma unroll
        for (int s = 0; s < 3; ++s) { bd[r][s] = 3.0e38f; bj[r][s] = INT_MAX; }

    const float4* hi4 = reinterpret_cast<const float4*>(g_hi);
    const float4* lo4 = reinterpret_cast<const float4*>(g_lo);

    for (int jt = 0; jt < 32; ++jt) {
        const int j0 = jbase + jt * 128;

        float acc[2][8][4];
        #pragma unroll
        for (int mf = 0; mf < 2; ++mf)
            #pragma unroll
            for (int nf = 0; nf < 8; ++nf)
                #pragma unroll
                for (int s = 0; s < 4; ++s) acc[mf][nf][s] = 0.f;

        for (int kc = 0; kc < C; kc += KC) {
            const int kq = kc >> 2;
            #pragma unroll
            for (int q = 0; q < 8; ++q) {
                int e = tid + 256 * q;
                int r = e >> 4, c4 = e & 15;
                float4 va = hi4[(size_t)(i0 + r) * 64 + kq + c4];
                *reinterpret_cast<float4*>(Ah + r * ASTR + 4 * c4) = va;
                float4 vb = lo4[(size_t)(i0 + r) * 64 + kq + c4];
                *reinterpret_cast<float4*>(Al + r * ASTR + 4 * c4) = vb;
                float4 vc = hi4[(size_t)(j0 + r) * 64 + kq + c4];
                *reinterpret_cast<float4*>(Bh + r * ASTR + 4 * c4) = vc;
                float4 vd = lo4[(size_t)(j0 + r) * 64 + kq + c4];
                *reinterpret_cast<float4*>(Bl + r * ASTR + 4 * c4) = vd;
            }
            __syncthreads();

            #pragma unroll
            for (int ks = 0; ks < KC / 8; ++ks) {
                const int k0 = ks * 8;
                uint32_t ah[2][4], al[2][4];
                #pragma unroll
                for (int mf = 0; mf < 2; ++mf) {
                    const int r0 = (warp_m * 32 + mf * 16 + qr) * ASTR;
                    ah[mf][0] = __float_as_uint(Ah[r0 + k0 + tq]);
                    ah[mf][1] = __float_as_uint(Ah[r0 + 8 * ASTR + k0 + tq]);
                    ah[mf][2] = __float_as_uint(Ah[r0 + k0 + 4 + tq]);
                    ah[mf][3] = __float_as_uint(Ah[r0 + 8 * ASTR + k0 + 4 + tq]);
                    al[mf][0] = __float_as_uint(Al[r0 + k0 + tq]);
                    al[mf][1] = __float_as_uint(Al[r0 + 8 * ASTR + k0 + tq]);
                    al[mf][2] = __float_as_uint(Al[r0 + k0 + 4 + tq]);
                    al[mf][3] = __float_as_uint(Al[r0 + 8 * ASTR + k0 + 4 + tq]);
                }
                uint32_t bh[8][2], bl[8][2];
                #pragma unroll
                for (int nf = 0; nf < 8; ++nf) {
                    const int c0 = (warp_n * 64 + nf * 8 + qr) * ASTR;
                    bh[nf][0] = __float_as_uint(Bh[c0 + k0 + tq]);
                    bh[nf][1] = __float_as_uint(Bh[c0 + k0 + 4 + tq]);
                    bl[nf][0] = __float_as_uint(Bl[c0 + k0 + tq]);
                    bl[nf][1] = __float_as_uint(Bl[c0 + k0 + 4 + tq]);
                }
                #pragma unroll
                for (int mf = 0; mf < 2; ++mf)
                    #pragma unroll
                    for (int nf = 0; nf < 8; ++nf) {
                        mma_tf32(acc[mf][nf], ah[mf], bh[nf]);
                        mma_tf32(acc[mf][nf], ah[mf], bl[nf]);
                        mma_tf32(acc[mf][nf], al[mf], bh[nf]);
                    }
            }
            __syncthreads();
        }

        #pragma unroll
        for (int mf = 0; mf < 2; ++mf)
            #pragma unroll
            for (int nf = 0; nf < 8; ++nf)
                #pragma unroll
                for (int s = 0; s < 4; ++s) {
                    const int hf = s >> 1;
                    const int col = warp_n * 64 + nf * 8 + 2 * tq + (s & 1);
                    const int j = j0 + col;
                    const float d = sqi[mf * 2 + hf] + g_sq[j] - 2.0f * acc[mf][nf][s];
                    insert3(d, j, bd[mf * 2 + hf], bj[mf * 2 + hf]);
                }
    }

    __syncthreads();
    float* cd = smem;
    int*   cj = reinterpret_cast<int*>(smem + 128 * 24);
    const int contrib = tq + 4 * warp_n;
    #pragma unroll
    for (int mf = 0; mf < 2; ++mf)
        #pragma unroll
        for (int hf = 0; hf < 2; ++hf) {
            const int row = warp_m * 32 + mf * 16 + 8 * hf + qr;
            #pragma unroll
            for (int s = 0; s < 3; ++s) {
                cd[row * 24 + contrib * 3 + s] = bd[mf * 2 + hf][s];
                cj[row * 24 + contrib * 3 + s] = bj[mf * 2 + hf][s];
            }
        }
    __syncthreads();
    if (tid < 128) {
        float fd[KCAND];
        int   fj[KCAND];
        #pragma unroll
        for (int s = 0; s < KCAND; ++s) { fd[s] = 3.0e38f; fj[s] = INT_MAX; }
        for (int c = 0; c < 24; ++c)
            insertK(cd[tid * 24 + c], cj[tid * 24 + c], fd, fj, KCAND);
        const size_t base = ((size_t)blockIdx.y * N + i0 + tid) * KCAND;
        #pragma unroll
        for (int s = 0; s < KCAND; ++s) {
            g_part_d[base + s] = fd[s];
            g_part_j[base + s] = fj[s];
        }
    }
}

// ---------------- exact fp32 rescore + final top-3 (proven R14) ----------------
__global__ void __launch_bounds__(256) rescore_kernel() {
    const int tid = threadIdx.x;
    const int wid = tid >> 5, lane = tid & 31;
    const int i = blockIdx.x * 8 + wid;

    float pi[8];
    #pragma unroll
    for (int q = 0; q < 8; ++q) pi[q] = g_p[(size_t)i * C + lane + 32 * q];
    const float sqi = g_sq[i];

    float bd[3] = {3.0e38f, 3.0e38f, 3.0e38f};
    int   bj[3] = {INT_MAX, INT_MAX, INT_MAX};

    for (int sp = 0; sp < 2; ++sp) {
        #pragma unroll
        for (int s = 0; s < KCAND; ++s) {
            const int j = g_part_j[((size_t)sp * N + i) * KCAND + s];
            float a = 0.f;
            #pragma unroll
            for (int q = 0; q < 8; ++q)
                a = fmaf(pi[q], g_p[(size_t)j * C + lane + 32 * q], a);
            #pragma unroll
            for (int off = 16; off; off >>= 1)
                a += __shfl_xor_sync(~0u, a, off);
            const float d = sqi + g_sq[j] - 2.0f * a;
            insert3(d, j, bd, bj);
        }
    }

    if (lane == 0) {
        #pragma unroll
        for (int s = 0; s < 3; ++s)
            g_idx[i * KNBR + s] = (bd[s] <= R2) ? bj[s] : -1;
    }
}

// ---------------- transpose (proven) ----------------
__global__ void nv_transpose(const float* __restrict__ W, float* __restrict__ WT) {
    int o = blockIdx.x;
    int k = threadIdx.x;
    WT[k * C + o] = W[o * C + k];
}

// ---------------- h = relu(x @ W1^T + b1), 16 rows per block (nv-style) ----------------
__global__ void __launch_bounds__(256) nv_h16(const float* __restrict__ x,
                                              const float* __restrict__ b1) {
    __shared__ float xs[16][257];
    const int o = threadIdx.x;
    const int i0 = blockIdx.x * 16;
    #pragma unroll
    for (int r = 0; r < 16; ++r) xs[r][o] = x[(size_t)(i0 + r) * C + o];
    __syncthreads();
    float acc[16];
    const float b = b1[o];
    #pragma unroll
    for (int r = 0; r < 16; ++r) acc[r] = b;
    for (int k = 0; k < C; ++k) {
        const float w = g_W1T[k * C + o];
        #pragma unroll
        for (int r = 0; r < 16; ++r) acc[r] = fmaf(xs[r][k], w, acc[r]);
    }
    #pragma unroll
    for (int r = 0; r < 16; ++r)
        g_h[(size_t)(i0 + r) * C + o] = fmaxf(acc[r], 0.f);
}

// ---------------- x1 = relu(agg @ Wrel^T + brel + h @ Wroot^T), 16 rows/block ----------------
__global__ void __launch_bounds__(256) nv_x116(const float* __restrict__ brel,
                                               float* __restrict__ x1) {
    __shared__ float as_[16][257];
    __shared__ float hs[16][257];
    const int o = threadIdx.x;
    const int i0 = blockIdx.x * 16;
    #pragma unroll
    for (int r = 0; r < 16; ++r) {
        as_[r][o] = g_agg[(size_t)(i0 + r) * C + o];
        hs[r][o]  = g_h[(size_t)(i0 + r) * C + o];
    }
    __syncthreads();
    float acc[16];
    const float b = brel[o];
    #pragma unroll
    for (int r = 0; r < 16; ++r) acc[r] = b;
    for (int k = 0; k < C; ++k) {
        const float wa = g_WrelT[k * C + o];
        const float wb = g_WrootT[k * C + o];
        #pragma unroll
        for (int r = 0; r < 16; ++r)
            acc[r] = fmaf(as_[r][k], wa, fmaf(hs[r][k], wb, acc[r]));
    }
    #pragma unroll
    for (int r = 0; r < 16; ++r)
        x1[(size_t)(i0 + r) * C + o] = fmaxf(acc[r], 0.f);
}

// ---------------- neighbor aggregation (proven) ----------------
__global__ void nv_agg() {
    int i = blockIdx.x, c2 = threadIdx.x;
    float a = 0.f;
    for (int k = 0; k < KNBR; ++k) {
        int j = g_idx[i * KNBR + k];
        if (j >= 0) a += g_h[(size_t)j * C + c2];
    }
    g_agg[(size_t)i * C + c2] = a;
}

// ---------------- out = x1 @ W2^T + b2 (proven) ----------------
__global__ void nv_head(const float* __restrict__ x1, const float* __restrict__ W2,
                        const float* __restrict__ b2, float* __restrict__ out) {
    int i = blockIdx.x, t = threadIdx.x;
    __shared__ float xs[C];
    xs[t] = x1[(size_t)i * C + t];
    __syncthreads();
    if (t == 0) {
        for (int cls = 0; cls < NCLS; ++cls) {
            float a = b2[cls];
            for (int k = 0; k < C; ++k) a += xs[k] * W2[cls * C + k];
            out[i * NCLS + cls] = a;
        }
    }
}

// ---------------- launch ----------------
extern "C" void kernel_launch(void* const* d_in, const int* in_sizes, int n_in,
                              void* d_out, int out_size) {
    const float *x = 0, *W1 = 0, *b1 = 0, *Wrel = 0, *brel = 0, *Wroot = 0, *W2 = 0, *b2 = 0;
    int nw = 0, nb = 0;
    for (int i = 0; i < n_in; ++i) {
        const float* p = (const float*)d_in[i];
        const int s = in_sizes[i];
        if (s == N * C) x = p;
        else if (s == C * C) { if (nw == 0) W1 = p; else if (nw == 1) Wrel = p; else Wroot = p; ++nw; }
        else if (s == C) { if (nb == 0) b1 = p; else brel = p; ++nb; }
        else if (s == NCLS * C) W2 = p;
        else if (s == NCLS) b2 = p;
    }

    float *x1dst, *outdst;
    float *x1_scr, *out_scr;
    cudaGetSymbolAddress((void**)&x1_scr, g_x1s);
    cudaGetSymbolAddress((void**)&out_scr, g_outs);
    if (out_size >= N * NCLS + N * C) {
        outdst = (float*)d_out;
        x1dst  = outdst + (size_t)N * NCLS;
    } else if (out_size == N * C) {
        x1dst  = (float*)d_out;
        outdst = out_scr;
    } else {
        outdst = (float*)d_out;
        x1dst  = x1_scr;
    }

    float *w1t, *wrelt, *wroott;
    cudaGetSymbolAddress((void**)&w1t, g_W1T);
    cudaGetSymbolAddress((void**)&wrelt, g_WrelT);
    cudaGetSymbolAddress((void**)&wroott, g_WrootT);

    cudaFuncSetAttribute(dist_tc32_kernel,
                         cudaFuncAttributeMaxDynamicSharedMemorySize, SM_DIST_BYTES);

    nv_transpose<<<C, C>>>(W1, w1t);
    nv_transpose<<<C, C>>>(Wrel, wrelt);
    nv_transpose<<<C, C>>>(Wroot, wroott);
    nv_softmax<<<N, C>>>(x);
    split_tf32_kernel<<<N, C>>>();
    nv_h16<<<N / 16, C>>>(x, b1);
    dist_tc32_kernel<<<dim3(N / 128, 2), 256, SM_DIST_BYTES>>>();
    rescore_kernel<<<N / 8, 256>>>();
    nv_agg<<<N, C>>>();
    nv_x116<<<N / 16, C>>>(brel, x1dst);
    nv_head<<<N, C>>>(x1dst, W2, b2, outdst);
}

// round 17
// speedup vs baseline: 5.9047x; 1.3281x over previous
#include <cuda_runtime.h>
#include <math.h>
#include <limits.h>
#include <stdint.h>

#define N 8192
#define C 256
#define NCLS 2
#define KNBR 3
#define KCAND 8
#define R2 9.0f

#define KC 64
#define ASTR 68
#define PLANE (128 * ASTR)
#define SM_DIST_BYTES (2 * PLANE * 4)   // hi-only: Ah + Bh

__device__ float g_p[N * C];
__device__ float g_hi[N * C];
__device__ float g_sq[N];
__device__ float g_h[N * C];
__device__ float g_agg[N * C];
__device__ float g_x1s[N * C];
__device__ float g_outs[N * NCLS];
__device__ int   g_idx[N * KNBR];
__device__ float g_W1T[C * C];
__device__ float g_WrelT[C * C];
__device__ float g_WrootT[C * C];
__device__ float g_part_d[2 * N * KCAND];
__device__ int   g_part_j[2 * N * KCAND];

__device__ __forceinline__ void insert3(float d, int j, float bd[3], int bj[3]) {
    bool l2 = (d < bd[2]) || (d == bd[2] && j < bj[2]);
    if (!l2) return;
    bool l1 = (d < bd[1]) || (d == bd[1] && j < bj[1]);
    bool l0 = (d < bd[0]) || (d == bd[0] && j < bj[0]);
    if (l0) {
        bd[2] = bd[1]; bj[2] = bj[1];
        bd[1] = bd[0]; bj[1] = bj[0];
        bd[0] = d;     bj[0] = j;
    } else if (l1) {
        bd[2] = bd[1]; bj[2] = bj[1];
        bd[1] = d;     bj[1] = j;
    } else {
        bd[2] = d;     bj[2] = j;
    }
}

__device__ __forceinline__ void insertK(float d, int j, float* bd, int* bj, int K) {
    if (!((d < bd[K - 1]) || (d == bd[K - 1] && j < bj[K - 1]))) return;
    bd[K - 1] = d; bj[K - 1] = j;
    for (int s = K - 1; s > 0; --s) {
        bool sw = (bd[s] < bd[s - 1]) || (bd[s] == bd[s - 1] && bj[s] < bj[s - 1]);
        if (!sw) break;
        float td = bd[s]; bd[s] = bd[s - 1]; bd[s - 1] = td;
        int tj = bj[s]; bj[s] = bj[s - 1]; bj[s - 1] = tj;
    }
}

__device__ __forceinline__ void mma_tf32(float* c, const uint32_t* a, const uint32_t* b) {
    asm volatile(
        "mma.sync.aligned.m16n8k8.row.col.f32.tf32.tf32.f32 "
        "{%0,%1,%2,%3}, {%4,%5,%6,%7}, {%8,%9}, {%0,%1,%2,%3};"
        : "+f"(c[0]), "+f"(c[1]), "+f"(c[2]), "+f"(c[3])
        : "r"(a[0]), "r"(a[1]), "r"(a[2]), "r"(a[3]), "r"(b[0]), "r"(b[1]));
}

// ---------------- softmax + sq norms (proven, untouched) ----------------
__global__ void nv_softmax(const float* __restrict__ x) {
    int i = blockIdx.x;
    int t = threadIdx.x;
    __shared__ float row[C];
    row[t] = x[i * C + t];
    __syncthreads();
    if (t == 0) {
        float m = row[0];
        for (int k = 1; k < C; ++k) m = fmaxf(m, row[k]);
        float s = 0.f;
        for (int k = 0; k < C; ++k) { row[k] = expf(row[k] - m); s += row[k]; }
        float sq = 0.f;
        for (int k = 0; k < C; ++k) {
            float p = row[k] / s;
            g_p[i * C + k] = p;
            sq += p * p;
        }
        g_sq[i] = sq;
    }
}

// ---------------- split p -> tf32 hi (prefilter metric) ----------------
__global__ void split_tf32_kernel() {
    const int i = blockIdx.x;
    const int k = threadIdx.x;
    float p = g_p[i * C + k];
    uint32_t hb;
    asm("cvt.rna.tf32.f32 %0, %1;" : "=r"(hb) : "f"(p));
    g_hi[i * C + k] = __uint_as_float(hb);
}

// ---------------- hi-only TF32 candidate generation ----------------
// Structure identical to the R14-proven kernel minus the lo planes/products.
__global__ void __launch_bounds__(256) dist_tc32_kernel() {
    extern __shared__ float smem[];
    float* Ah = smem;
    float* Bh = smem + PLANE;

    const int tid = threadIdx.x;
    const int wid = tid >> 5, lane = tid & 31;
    const int warp_m = wid & 3, warp_n = wid >> 2;
    const int qr = lane >> 2, tq = lane & 3;
    const int i0 = blockIdx.x * 128;
    const int jbase = blockIdx.y * 4096;

    float sqi[4];
    #pragma unroll
    for (int mf = 0; mf < 2; ++mf)
        #pragma unroll
        for (int hf = 0; hf < 2; ++hf)
            sqi[mf * 2 + hf] = g_sq[i0 + warp_m * 32 + mf * 16 + 8 * hf + qr];

    float bd[4][3];
    int   bj[4][3];
    #pragma unroll
    for (int r = 0; r < 4; ++r)
        #pragma unroll
        for (int s = 0; s < 3; ++s) { bd[r][s] = 3.0e38f; bj[r][s] = INT_MAX; }

    const float4* hi4 = reinterpret_cast<const float4*>(g_hi);

    for (int jt = 0; jt < 32; ++jt) {
        const int j0 = jbase + jt * 128;

        float acc[2][8][4];
        #pragma unroll
        for (int mf = 0; mf < 2; ++mf)
            #pragma unroll
            for (int nf = 0; nf < 8; ++nf)
                #pragma unroll
                for (int s = 0; s < 4; ++s) acc[mf][nf][s] = 0.f;

        for (int kc = 0; kc < C; kc += KC) {
            const int kq = kc >> 2;
            #pragma unroll
            for (int q = 0; q < 8; ++q) {
                int e = tid + 256 * q;
                int r = e >> 4, c4 = e & 15;
                float4 va = hi4[(size_t)(i0 + r) * 64 + kq + c4];
                *reinterpret_cast<float4*>(Ah + r * ASTR + 4 * c4) = va;
                float4 vc = hi4[(size_t)(j0 + r) * 64 + kq + c4];
                *reinterpret_cast<float4*>(Bh + r * ASTR + 4 * c4) = vc;
            }
            __syncthreads();

            #pragma unroll
            for (int ks = 0; ks < KC / 8; ++ks) {
                const int k0 = ks * 8;
                uint32_t ah[2][4];
                #pragma unroll
                for (int mf = 0; mf < 2; ++mf) {
                    const int r0 = (warp_m * 32 + mf * 16 + qr) * ASTR;
                    ah[mf][0] = __float_as_uint(Ah[r0 + k0 + tq]);
                    ah[mf][1] = __float_as_uint(Ah[r0 + 8 * ASTR + k0 + tq]);
                    ah[mf][2] = __float_as_uint(Ah[r0 + k0 + 4 + tq]);
                    ah[mf][3] = __float_as_uint(Ah[r0 + 8 * ASTR + k0 + 4 + tq]);
                }
                uint32_t bh[8][2];
                #pragma unroll
                for (int nf = 0; nf < 8; ++nf) {
                    const int c0 = (warp_n * 64 + nf * 8 + qr) * ASTR;
                    bh[nf][0] = __float_as_uint(Bh[c0 + k0 + tq]);
                    bh[nf][1] = __float_as_uint(Bh[c0 + k0 + 4 + tq]);
                }
                #pragma unroll
                for (int mf = 0; mf < 2; ++mf)
                    #pragma unroll
                    for (int nf = 0; nf < 8; ++nf)
                        mma_tf32(acc[mf][nf], ah[mf], bh[nf]);
            }
            __syncthreads();
        }

        #pragma unroll
        for (int mf = 0; mf < 2; ++mf)
            #pragma unroll
            for (int nf = 0; nf < 8; ++nf)
                #pragma unroll
                for (int s = 0; s < 4; ++s) {
                    const int hf = s >> 1;
                    const int col = warp_n * 64 + nf * 8 + 2 * tq + (s & 1);
                    const int j = j0 + col;
                    const float d = sqi[mf * 2 + hf] + g_sq[j] - 2.0f * acc[mf][nf][s];
                    insert3(d, j, bd[mf * 2 + hf], bj[mf * 2 + hf]);
                }
    }

    // row-level reduction: 24 contributor candidates -> top-KCAND (prefilter metric)
    __syncthreads();
    float* cd = smem;
    int*   cj = reinterpret_cast<int*>(smem + 128 * 24);
    const int contrib = tq + 4 * warp_n;
    #pragma unroll
    for (int mf = 0; mf < 2; ++mf)
        #pragma unroll
        for (int hf = 0; hf < 2; ++hf) {
            const int row = warp_m * 32 + mf * 16 + 8 * hf + qr;
            #pragma unroll
            for (int s = 0; s < 3; ++s) {
                cd[row * 24 + contrib * 3 + s] = bd[mf * 2 + hf][s];
                cj[row * 24 + contrib * 3 + s] = bj[mf * 2 + hf][s];
            }
        }
    __syncthreads();
    if (tid < 128) {
        float fd[KCAND];
        int   fj[KCAND];
        #pragma unroll
        for (int s = 0; s < KCAND; ++s) { fd[s] = 3.0e38f; fj[s] = INT_MAX; }
        for (int c = 0; c < 24; ++c)
            insertK(cd[tid * 24 + c], cj[tid * 24 + c], fd, fj, KCAND);
        const size_t base = ((size_t)blockIdx.y * N + i0 + tid) * KCAND;
        #pragma unroll
        for (int s = 0; s < KCAND; ++s) {
            g_part_d[base + s] = fd[s];
            g_part_j[base + s] = fj[s];
        }
    }
}

// ---------------- exact fp32 rescore + final top-3 (proven) ----------------
__global__ void __launch_bounds__(256) rescore_kernel() {
    const int tid = threadIdx.x;
    const int wid = tid >> 5, lane = tid & 31;
    const int i = blockIdx.x * 8 + wid;

    float pi[8];
    #pragma unroll
    for (int q = 0; q < 8; ++q) pi[q] = g_p[(size_t)i * C + lane + 32 * q];
    const float sqi = g_sq[i];

    float bd[3] = {3.0e38f, 3.0e38f, 3.0e38f};
    int   bj[3] = {INT_MAX, INT_MAX, INT_MAX};

    for (int sp = 0; sp < 2; ++sp) {
        #pragma unroll
        for (int s = 0; s < KCAND; ++s) {
            const int j = g_part_j[((size_t)sp * N + i) * KCAND + s];
            float a = 0.f;
            #pragma unroll
            for (int q = 0; q < 8; ++q)
                a = fmaf(pi[q], g_p[(size_t)j * C + lane + 32 * q], a);
            #pragma unroll
            for (int off = 16; off; off >>= 1)
                a += __shfl_xor_sync(~0u, a, off);
            const float d = sqi + g_sq[j] - 2.0f * a;
            insert3(d, j, bd, bj);
        }
    }

    if (lane == 0) {
        #pragma unroll
        for (int s = 0; s < 3; ++s)
            g_idx[i * KNBR + s] = (bd[s] <= R2) ? bj[s] : -1;
    }
}

// ---------------- transpose (proven) ----------------
__global__ void nv_transpose(const float* __restrict__ W, float* __restrict__ WT) {
    int o = blockIdx.x;
    int k = threadIdx.x;
    WT[k * C + o] = W[o * C + k];
}

// ---------------- h = relu(x @ W1^T + b1), 16 rows/block (proven R16) ----------------
__global__ void __launch_bounds__(256) nv_h16(const float* __restrict__ x,
                                              const float* __restrict__ b1) {
    __shared__ float xs[16][257];
    const int o = threadIdx.x;
    const int i0 = blockIdx.x * 16;
    #pragma unroll
    for (int r = 0; r < 16; ++r) xs[r][o] = x[(size_t)(i0 + r) * C + o];
    __syncthreads();
    float acc[16];
    const float b = b1[o];
    #pragma unroll
    for (int r = 0; r < 16; ++r) acc[r] = b;
    for (int k = 0; k < C; ++k) {
        const float w = g_W1T[k * C + o];
        #pragma unroll
        for (int r = 0; r < 16; ++r) acc[r] = fmaf(xs[r][k], w, acc[r]);
    }
    #pragma unroll
    for (int r = 0; r < 16; ++r)
        g_h[(size_t)(i0 + r) * C + o] = fmaxf(acc[r], 0.f);
}

// ---------------- x1 = relu(agg @ Wrel^T + brel + h @ Wroot^T), 16 rows/block (proven R16) ----
__global__ void __launch_bounds__(256) nv_x116(const float* __restrict__ brel,
                                               float* __restrict__ x1) {
    __shared__ float as_[16][257];
    __shared__ float hs[16][257];
    const int o = threadIdx.x;
    const int i0 = blockIdx.x * 16;
    #pragma unroll
    for (int r = 0; r < 16; ++r) {
        as_[r][o] = g_agg[(size_t)(i0 + r) * C + o];
        hs[r][o]  = g_h[(size_t)(i0 + r) * C + o];
    }
    __syncthreads();
    float acc[16];
    const float b = brel[o];
    #pragma unroll
    for (int r = 0; r < 16; ++r) acc[r] = b;
    for (int k = 0; k < C; ++k) {
        const float wa = g_WrelT[k * C + o];
        const float wb = g_WrootT[k * C + o];
        #pragma unroll
        for (int r = 0; r < 16; ++r)
            acc[r] = fmaf(as_[r][k], wa, fmaf(hs[r][k], wb, acc[r]));
    }
    #pragma unroll
    for (int r = 0; r < 16; ++r)
        x1[(size_t)(i0 + r) * C + o] = fmaxf(acc[r], 0.f);
}

// ---------------- neighbor aggregation (proven) ----------------
__global__ void nv_agg() {
    int i = blockIdx.x, c2 = threadIdx.x;
    float a = 0.f;
    for (int k = 0; k < KNBR; ++k) {
        int j = g_idx[i * KNBR + k];
        if (j >= 0) a += g_h[(size_t)j * C + c2];
    }
    g_agg[(size_t)i * C + c2] = a;
}

// ---------------- out = x1 @ W2^T + b2 (proven) ----------------
__global__ void nv_head(const float* __restrict__ x1, const float* __restrict__ W2,
                        const float* __restrict__ b2, float* __restrict__ out) {
    int i = blockIdx.x, t = threadIdx.x;
    __shared__ float xs[C];
    xs[t] = x1[(size_t)i * C + t];
    __syncthreads();
    if (t == 0) {
        for (int cls = 0; cls < NCLS; ++cls) {
            float a = b2[cls];
            for (int k = 0; k < C; ++k) a += xs[k] * W2[cls * C + k];
            out[i * NCLS + cls] = a;
        }
    }
}

// ---------------- launch ----------------
extern "C" void kernel_launch(void* const* d_in, const int* in_sizes, int n_in,
                              void* d_out, int out_size) {
    const float *x = 0, *W1 = 0, *b1 = 0, *Wrel = 0, *brel = 0, *Wroot = 0, *W2 = 0, *b2 = 0;
    int nw = 0, nb = 0;
    for (int i = 0; i < n_in; ++i) {
        const float* p = (const float*)d_in[i];
        const int s = in_sizes[i];
        if (s == N * C) x = p;
        else if (s == C * C) { if (nw == 0) W1 = p; else if (nw == 1) Wrel = p; else Wroot = p; ++nw; }
        else if (s == C) { if (nb == 0) b1 = p; else brel = p; ++nb; }
        else if (s == NCLS * C) W2 = p;
        else if (s == NCLS) b2 = p;
    }

    float *x1dst, *outdst;
    float *x1_scr, *out_scr;
    cudaGetSymbolAddress((void**)&x1_scr, g_x1s);
    cudaGetSymbolAddress((void**)&out_scr, g_outs);
    if (out_size >= N * NCLS + N * C) {
        outdst = (float*)d_out;
        x1dst  = outdst + (size_t)N * NCLS;
    } else if (out_size == N * C) {
        x1dst  = (float*)d_out;
        outdst = out_scr;
    } else {
        outdst = (float*)d_out;
        x1dst  = x1_scr;
    }

    float *w1t, *wrelt, *wroott;
    cudaGetSymbolAddress((void**)&w1t, g_W1T);
    cudaGetSymbolAddress((void**)&wrelt, g_WrelT);
    cudaGetSymbolAddress((void**)&wroott, g_WrootT);

    cudaFuncSetAttribute(dist_tc32_kernel,
                         cudaFuncAttributeMaxDynamicSharedMemorySize, SM_DIST_BYTES);

    nv_transpose<<<C, C>>>(W1, w1t);
    nv_transpose<<<C, C>>>(Wrel, wrelt);
    nv_transpose<<<C, C>>>(Wroot, wroott);
    nv_softmax<<<N, C>>>(x);
    split_tf32_kernel<<<N, C>>>();
    nv_h16<<<N / 16, C>>>(x, b1);
    dist_tc32_kernel<<<dim3(N / 128, 2), 256, SM_DIST_BYTES>>>();
    rescore_kernel<<<N / 8, 256>>>();
    nv_agg<<<N, C>>>();
    nv_x116<<<N / 16, C>>>(brel, x1dst);
    nv_head<<<N, C>>>(x1dst, W2, b2, outdst);
}